// round 7
// baseline (speedup 1.0000x reference)
#include <cuda_runtime.h>
#include <math.h>

#define B_    4
#define C_    128
#define N_    8192
#define CQK_  32
#define TN    64
#define TM    64

// -------- device scratch (allocation-free rule: __device__ globals) --------
__device__ float g_q  [B_ * CQK_ * N_];   // (B, 32, N)
__device__ float g_k  [B_ * CQK_ * N_];   // (B, 32, N)
__device__ float g_vt [B_ * N_   * C_];   // (B, N, 128)  V transposed
__device__ float g_pos[B_ * 3    * N_];   // (B, 3, N)    normalized xyz

// ===========================================================================
// Projection kernel: q = Wq x + bq, k = Wk x + bk, v = Wv x + bv (transposed),
// plus xyz normalization. One CTA handles 32 points of one batch.
// ===========================================================================
__global__ __launch_bounds__(256) void proj_kernel(
    const float* __restrict__ x,  const float* __restrict__ xyz,
    const float* __restrict__ Wq, const float* __restrict__ bq,
    const float* __restrict__ Wk, const float* __restrict__ bk,
    const float* __restrict__ Wv, const float* __restrict__ bv)
{
    __shared__ float xs [32][132];   // x tile, [point][channel], padded
    __shared__ float stg[32][129];   // V transpose staging

    const int b  = blockIdx.y;
    const int n0 = blockIdx.x * 32;
    const int t  = threadIdx.x;

    const float* xb = x + b * C_ * N_;
    // load x[:, n0:n0+32] tile (coalesced over n)
    for (int idx = t; idx < C_ * 32; idx += 256) {
        int c = idx >> 5, j = idx & 31;
        xs[j][c] = xb[c * N_ + n0 + j];
    }
    // normalized xyz
    if (t < 32) {
        const float* p = xyz + (b * N_ + n0 + t) * 3;
        float px = p[0], py = p[1], pz = p[2];
        float inv = 1.0f / (sqrtf(px*px + py*py + pz*pz) + 1e-8f);
        g_pos[(b*3 + 0) * N_ + n0 + t] = px * inv;
        g_pos[(b*3 + 1) * N_ + n0 + t] = py * inv;
        g_pos[(b*3 + 2) * N_ + n0 + t] = pz * inv;
    }
    __syncthreads();

    const int j = t & 31;    // point within tile
    const int g = t >> 5;    // output group (warp id)

    // ---- pass 1: q (o<32) and k (o in 32..63), 8 outputs per thread ----
    {
        float acc[8] = {0.f,0.f,0.f,0.f,0.f,0.f,0.f,0.f};
        #pragma unroll 4
        for (int cc = 0; cc < 32; cc++) {
            float4 xv = *reinterpret_cast<const float4*>(&xs[j][cc * 4]);
            #pragma unroll
            for (int i = 0; i < 8; i++) {
                int o = g * 8 + i;
                const float* Wrow = (o < 32) ? (Wq + o * C_) : (Wk + (o - 32) * C_);
                float4 w = *reinterpret_cast<const float4*>(Wrow + cc * 4);
                acc[i] = fmaf(w.x, xv.x, fmaf(w.y, xv.y,
                         fmaf(w.z, xv.z, fmaf(w.w, xv.w, acc[i]))));
            }
        }
        #pragma unroll
        for (int i = 0; i < 8; i++) {
            int o = g * 8 + i;
            if (o < 32) g_q[(b * CQK_ +  o      ) * N_ + n0 + j] = acc[i] + bq[o];
            else        g_k[(b * CQK_ + (o - 32)) * N_ + n0 + j] = acc[i] + bk[o - 32];
        }
    }

    // ---- pass 2: v, 16 channels per thread, store transposed via smem ----
    {
        float acc[16];
        #pragma unroll
        for (int i = 0; i < 16; i++) acc[i] = 0.f;
        #pragma unroll 2
        for (int cc = 0; cc < 32; cc++) {
            float4 xv = *reinterpret_cast<const float4*>(&xs[j][cc * 4]);
            #pragma unroll
            for (int i = 0; i < 16; i++) {
                const float* Wrow = Wv + (g * 16 + i) * C_;
                float4 w = *reinterpret_cast<const float4*>(Wrow + cc * 4);
                acc[i] = fmaf(w.x, xv.x, fmaf(w.y, xv.y,
                         fmaf(w.z, xv.z, fmaf(w.w, xv.w, acc[i]))));
            }
        }
        #pragma unroll
        for (int i = 0; i < 16; i++)
            stg[j][g * 16 + i] = acc[i] + bv[g * 16 + i];
        __syncthreads();
        // coalesced transposed store: g_vt[b][n][c]
        for (int idx = t; idx < 32 * C_; idx += 256) {
            int jj = idx >> 7, c = idx & 127;
            g_vt[(b * N_ + n0 + jj) * C_ + c] = stg[jj][c];
        }
    }
}

// ===========================================================================
// Fused flash-attention kernel. One CTA = 64 queries of one batch.
// smem floats: qs 64*33 | ks 64*33 | vs 64*132 | S 64*65 | pq 3*64 | pk 3*64
//              | Mrow 64 | Lrow 64 | rsc 64   == 17408 floats (69632 B)
// ===========================================================================
#define SMEM_FLOATS (TN*33 + TM*33 + TM*132 + TN*65 + 3*TN + 3*TM + 3*TN)

__global__ __launch_bounds__(256, 2) void attn_kernel(
    const float* __restrict__ x, const float* __restrict__ gamma,
    float* __restrict__ out)
{
    extern __shared__ float sm[];
    float* qs   = sm;                 // [64][33]
    float* ks   = qs + TN * 33;      // [64][33]
    float* vs   = ks + TM * 33;      // [64][132]
    float* S    = vs + TM * 132;     // [64][65]  scores -> probs -> out staging
    float* pq   = S  + TN * 65;      // [3][64]
    float* pk   = pq + 3 * TN;       // [3][64]
    float* Mrow = pk + 3 * TM;       // [64]
    float* Lrow = Mrow + TN;         // [64]
    float* rsc  = Lrow + TN;         // [64]

    const int b  = blockIdx.y;
    const int n0 = blockIdx.x * TN;
    const int t  = threadIdx.x;
    const int w  = t >> 5, l = t & 31;
    const int tx = t & 15, ty = t >> 4;

    // load Q tile (coalesced over n)
    const float* qb = g_q + b * CQK_ * N_;
    for (int idx = t; idx < TN * CQK_; idx += 256) {
        int c = idx >> 6, r = idx & 63;
        qs[r * 33 + c] = qb[c * N_ + n0 + r];
    }
    if (t < TN) {
        pq[0*TN + t] = g_pos[(b*3 + 0) * N_ + n0 + t];
        pq[1*TN + t] = g_pos[(b*3 + 1) * N_ + n0 + t];
        pq[2*TN + t] = g_pos[(b*3 + 2) * N_ + n0 + t];
        Mrow[t] = -1e30f;
        Lrow[t] = 0.f;
    }

    float acc[8][4];
    #pragma unroll
    for (int i = 0; i < 8; i++)
        #pragma unroll
        for (int e = 0; e < 4; e++) acc[i][e] = 0.f;

    const float* kb = g_k + b * CQK_ * N_;

    for (int m0 = 0; m0 < N_; m0 += TM) {
        __syncthreads();   // previous iteration's consumers done with ks/vs/S

        // load K tile
        for (int idx = t; idx < TM * CQK_; idx += 256) {
            int c = idx >> 6, r = idx & 63;
            ks[r * 33 + c] = kb[c * N_ + m0 + r];
        }
        // load V tile (transposed source -> conflict-free float4 STS)
        for (int idx = t; idx < TM * 32; idx += 256) {
            int m = idx >> 5, c4 = (idx & 31) << 2;
            float4 v = *reinterpret_cast<const float4*>(
                &g_vt[(b * N_ + m0 + m) * C_ + c4]);
            *reinterpret_cast<float4*>(&vs[m * 132 + c4]) = v;
        }
        if (t < TM) {
            pk[0*TM + t] = g_pos[(b*3 + 0) * N_ + m0 + t];
            pk[1*TM + t] = g_pos[(b*3 + 1) * N_ + m0 + t];
            pk[2*TM + t] = g_pos[(b*3 + 2) * N_ + m0 + t];
        }
        __syncthreads();

        // ---- phase A: S = Q K^T + 0.1 * pos_corr (4x4 register block) ----
        float s[4][4];
        #pragma unroll
        for (int i = 0; i < 4; i++)
            #pragma unroll
            for (int jj = 0; jj < 4; jj++) s[i][jj] = 0.f;

        #pragma unroll 4
        for (int c = 0; c < CQK_; c++) {
            float a[4], bb[4];
            #pragma unroll
            for (int i = 0; i < 4; i++)  a[i]  = qs[(4*ty + i) * 33 + c];
            #pragma unroll
            for (int jj = 0; jj < 4; jj++) bb[jj] = ks[(4*tx + jj) * 33 + c];
            #pragma unroll
            for (int i = 0; i < 4; i++)
                #pragma unroll
                for (int jj = 0; jj < 4; jj++)
                    s[i][jj] = fmaf(a[i], bb[jj], s[i][jj]);
        }
        #pragma unroll
        for (int i = 0; i < 4; i++) {
            float px = pq[0*TN + 4*ty + i];
            float py = pq[1*TN + 4*ty + i];
            float pz = pq[2*TN + 4*ty + i];
            #pragma unroll
            for (int jj = 0; jj < 4; jj++) {
                float d = px * pk[0*TM + 4*tx + jj]
                        + py * pk[1*TM + 4*tx + jj]
                        + pz * pk[2*TM + 4*tx + jj];
                s[i][jj] += 0.1f * d;
            }
        }
        #pragma unroll
        for (int i = 0; i < 4; i++)
            #pragma unroll
            for (int jj = 0; jj < 4; jj++)
                S[(4*ty + i) * 65 + 4*tx + jj] = s[i][jj];
        __syncthreads();

        // ---- row stats + exp (online softmax) ----
        if (t < TN) {
            int r = t;
            float old = Mrow[r];
            float mx  = old;
            #pragma unroll 8
            for (int jj = 0; jj < TM; jj++) mx = fmaxf(mx, S[r * 65 + jj]);
            float rs  = __expf(old - mx);
            float sum = 0.f;
            #pragma unroll 8
            for (int jj = 0; jj < TM; jj++) {
                float p = __expf(S[r * 65 + jj] - mx);
                S[r * 65 + jj] = p;
                sum += p;
            }
            Lrow[r] = Lrow[r] * rs + sum;
            Mrow[r] = mx;
            rsc[r]  = rs;
        }
        __syncthreads();

        // ---- rescale accumulators ----
        #pragma unroll
        for (int qi = 0; qi < 8; qi++) {
            float rr = rsc[w * 8 + qi];
            acc[qi][0] *= rr; acc[qi][1] *= rr;
            acc[qi][2] *= rr; acc[qi][3] *= rr;
        }

        // ---- phase B: acc += P * V (float4 V, broadcast P) ----
        #pragma unroll 2
        for (int m = 0; m < TM; m++) {
            float4 v4 = *reinterpret_cast<const float4*>(&vs[m * 132 + 4 * l]);
            #pragma unroll
            for (int qi = 0; qi < 8; qi++) {
                float p = S[(w * 8 + qi) * 65 + m];
                acc[qi][0] = fmaf(p, v4.x, acc[qi][0]);
                acc[qi][1] = fmaf(p, v4.y, acc[qi][1]);
                acc[qi][2] = fmaf(p, v4.z, acc[qi][2]);
                acc[qi][3] = fmaf(p, v4.w, acc[qi][3]);
            }
        }
    }

    // ---- epilogue: out = gamma * acc / L + x, transposed store via smem ----
    float gm = gamma[0];
    float fac[8];
    #pragma unroll
    for (int qi = 0; qi < 8; qi++) fac[qi] = gm / Lrow[w * 8 + qi];

    const float* xb = x + b * C_ * N_;
    #pragma unroll
    for (int cg = 0; cg < 2; cg++) {
        __syncthreads();   // S free to reuse as staging
        if ((l >> 4) == cg) {
            #pragma unroll
            for (int qi = 0; qi < 8; qi++)
                #pragma unroll
                for (int e = 0; e < 4; e++)
                    S[(w * 8 + qi) * 65 + (4 * l + e - cg * 64)] = acc[qi][e] * fac[qi];
        }
        __syncthreads();
        for (int idx = t; idx < 64 * 64; idx += 256) {
            int cl = idx >> 6, nl = idx & 63;
            int c  = cg * 64 + cl;
            out[(b * C_ + c) * N_ + n0 + nl] =
                S[nl * 65 + cl] + xb[c * N_ + n0 + nl];
        }
    }
}

// ===========================================================================
extern "C" void kernel_launch(void* const* d_in, const int* in_sizes, int n_in,
                              void* d_out, int out_size)
{
    (void)in_sizes; (void)n_in; (void)out_size;
    const float* x     = (const float*)d_in[0];
    const float* xyz   = (const float*)d_in[1];
    const float* Wq    = (const float*)d_in[2];
    const float* bq    = (const float*)d_in[3];
    const float* Wk    = (const float*)d_in[4];
    const float* bk    = (const float*)d_in[5];
    const float* Wv    = (const float*)d_in[6];
    const float* bv    = (const float*)d_in[7];
    const float* gamma = (const float*)d_in[8];
    float* out = (float*)d_out;

    // opt-in to >48KB dynamic smem (idempotent, not a stream op — capture-safe)
    cudaFuncSetAttribute(attn_kernel,
                         cudaFuncAttributeMaxDynamicSharedMemorySize,
                         SMEM_FLOATS * (int)sizeof(float));

    dim3 pg(N_ / 32, B_);
    proj_kernel<<<pg, 256>>>(x, xyz, Wq, bq, Wk, bk, Wv, bv);

    dim3 ag(N_ / TN, B_);
    attn_kernel<<<ag, 256, SMEM_FLOATS * sizeof(float)>>>(x, gamma, out);
}

// round 8
// speedup vs baseline: 1.0004x; 1.0004x over previous
#include <cuda_runtime.h>
#include <math.h>

#define B_    4
#define C_    128
#define N_    8192
#define CQK_  32
#define TN    64
#define TM    64

// -------- device scratch (allocation-free rule: __device__ globals) --------
__device__ float g_q  [B_ * CQK_ * N_];   // (B, 32, N)
__device__ float g_k  [B_ * CQK_ * N_];   // (B, 32, N)
__device__ float g_vt [B_ * N_   * C_];   // (B, N, 128)  V transposed
__device__ float g_pos[B_ * 3    * N_];   // (B, 3, N)    normalized xyz

// ===========================================================================
// Projection kernel: q = Wq x + bq, k = Wk x + bk, v = Wv x + bv (transposed),
// plus xyz normalization. One CTA handles 32 points of one batch.
// ===========================================================================
__global__ __launch_bounds__(256) void proj_kernel(
    const float* __restrict__ x,  const float* __restrict__ xyz,
    const float* __restrict__ Wq, const float* __restrict__ bq,
    const float* __restrict__ Wk, const float* __restrict__ bk,
    const float* __restrict__ Wv, const float* __restrict__ bv)
{
    __shared__ float xs [32][132];   // x tile, [point][channel], padded
    __shared__ float stg[32][129];   // V transpose staging

    const int b  = blockIdx.y;
    const int n0 = blockIdx.x * 32;
    const int t  = threadIdx.x;

    const float* xb = x + b * C_ * N_;
    // load x[:, n0:n0+32] tile (coalesced over n)
    for (int idx = t; idx < C_ * 32; idx += 256) {
        int c = idx >> 5, j = idx & 31;
        xs[j][c] = xb[c * N_ + n0 + j];
    }
    // normalized xyz
    if (t < 32) {
        const float* p = xyz + (b * N_ + n0 + t) * 3;
        float px = p[0], py = p[1], pz = p[2];
        float inv = 1.0f / (sqrtf(px*px + py*py + pz*pz) + 1e-8f);
        g_pos[(b*3 + 0) * N_ + n0 + t] = px * inv;
        g_pos[(b*3 + 1) * N_ + n0 + t] = py * inv;
        g_pos[(b*3 + 2) * N_ + n0 + t] = pz * inv;
    }
    __syncthreads();

    const int j = t & 31;    // point within tile
    const int g = t >> 5;    // output group (warp id)

    // ---- pass 1: q (o<32) and k (o in 32..63), 8 outputs per thread ----
    {
        float acc[8] = {0.f,0.f,0.f,0.f,0.f,0.f,0.f,0.f};
        #pragma unroll 4
        for (int cc = 0; cc < 32; cc++) {
            float4 xv = *reinterpret_cast<const float4*>(&xs[j][cc * 4]);
            #pragma unroll
            for (int i = 0; i < 8; i++) {
                int o = g * 8 + i;
                const float* Wrow = (o < 32) ? (Wq + o * C_) : (Wk + (o - 32) * C_);
                float4 w = *reinterpret_cast<const float4*>(Wrow + cc * 4);
                acc[i] = fmaf(w.x, xv.x, fmaf(w.y, xv.y,
                         fmaf(w.z, xv.z, fmaf(w.w, xv.w, acc[i]))));
            }
        }
        #pragma unroll
        for (int i = 0; i < 8; i++) {
            int o = g * 8 + i;
            if (o < 32) g_q[(b * CQK_ +  o      ) * N_ + n0 + j] = acc[i] + bq[o];
            else        g_k[(b * CQK_ + (o - 32)) * N_ + n0 + j] = acc[i] + bk[o - 32];
        }
    }

    // ---- pass 2: v, 16 channels per thread, store transposed via smem ----
    {
        float acc[16];
        #pragma unroll
        for (int i = 0; i < 16; i++) acc[i] = 0.f;
        #pragma unroll 2
        for (int cc = 0; cc < 32; cc++) {
            float4 xv = *reinterpret_cast<const float4*>(&xs[j][cc * 4]);
            #pragma unroll
            for (int i = 0; i < 16; i++) {
                const float* Wrow = Wv + (g * 16 + i) * C_;
                float4 w = *reinterpret_cast<const float4*>(Wrow + cc * 4);
                acc[i] = fmaf(w.x, xv.x, fmaf(w.y, xv.y,
                         fmaf(w.z, xv.z, fmaf(w.w, xv.w, acc[i]))));
            }
        }
        #pragma unroll
        for (int i = 0; i < 16; i++)
            stg[j][g * 16 + i] = acc[i] + bv[g * 16 + i];
        __syncthreads();
        // coalesced transposed store: g_vt[b][n][c]
        for (int idx = t; idx < 32 * C_; idx += 256) {
            int jj = idx >> 7, c = idx & 127;
            g_vt[(b * N_ + n0 + jj) * C_ + c] = stg[jj][c];
        }
    }
}

// ===========================================================================
// Fused flash-attention kernel. One CTA = 64 queries of one batch.
// smem floats: qs 64*33 | ks 64*33 | vs 64*132 | S 64*65 | pq 3*64 | pk 3*64
//              | Mrow 64 | Lrow 64 | rsc 64   == 17408 floats (69632 B)
// ===========================================================================
#define SMEM_FLOATS (TN*33 + TM*33 + TM*132 + TN*65 + 3*TN + 3*TM + 3*TN)

__global__ __launch_bounds__(256, 2) void attn_kernel(
    const float* __restrict__ x, const float* __restrict__ gamma,
    float* __restrict__ out)
{
    extern __shared__ float sm[];
    float* qs   = sm;                 // [64][33]
    float* ks   = qs + TN * 33;      // [64][33]
    float* vs   = ks + TM * 33;      // [64][132]
    float* S    = vs + TM * 132;     // [64][65]  scores -> probs -> out staging
    float* pq   = S  + TN * 65;      // [3][64]
    float* pk   = pq + 3 * TN;       // [3][64]
    float* Mrow = pk + 3 * TM;       // [64]
    float* Lrow = Mrow + TN;         // [64]
    float* rsc  = Lrow + TN;         // [64]

    const int b  = blockIdx.y;
    const int n0 = blockIdx.x * TN;
    const int t  = threadIdx.x;
    const int w  = t >> 5, l = t & 31;
    const int tx = t & 15, ty = t >> 4;

    // load Q tile (coalesced over n)
    const float* qb = g_q + b * CQK_ * N_;
    for (int idx = t; idx < TN * CQK_; idx += 256) {
        int c = idx >> 6, r = idx & 63;
        qs[r * 33 + c] = qb[c * N_ + n0 + r];
    }
    if (t < TN) {
        pq[0*TN + t] = g_pos[(b*3 + 0) * N_ + n0 + t];
        pq[1*TN + t] = g_pos[(b*3 + 1) * N_ + n0 + t];
        pq[2*TN + t] = g_pos[(b*3 + 2) * N_ + n0 + t];
        Mrow[t] = -1e30f;
        Lrow[t] = 0.f;
    }

    float acc[8][4];
    #pragma unroll
    for (int i = 0; i < 8; i++)
        #pragma unroll
        for (int e = 0; e < 4; e++) acc[i][e] = 0.f;

    const float* kb = g_k + b * CQK_ * N_;

    for (int m0 = 0; m0 < N_; m0 += TM) {
        __syncthreads();   // previous iteration's consumers done with ks/vs/S

        // load K tile
        for (int idx = t; idx < TM * CQK_; idx += 256) {
            int c = idx >> 6, r = idx & 63;
            ks[r * 33 + c] = kb[c * N_ + m0 + r];
        }
        // load V tile (transposed source -> conflict-free float4 STS)
        for (int idx = t; idx < TM * 32; idx += 256) {
            int m = idx >> 5, c4 = (idx & 31) << 2;
            float4 v = *reinterpret_cast<const float4*>(
                &g_vt[(b * N_ + m0 + m) * C_ + c4]);
            *reinterpret_cast<float4*>(&vs[m * 132 + c4]) = v;
        }
        if (t < TM) {
            pk[0*TM + t] = g_pos[(b*3 + 0) * N_ + m0 + t];
            pk[1*TM + t] = g_pos[(b*3 + 1) * N_ + m0 + t];
            pk[2*TM + t] = g_pos[(b*3 + 2) * N_ + m0 + t];
        }
        __syncthreads();

        // ---- phase A: S = Q K^T + 0.1 * pos_corr (4x4 register block) ----
        float s[4][4];
        #pragma unroll
        for (int i = 0; i < 4; i++)
            #pragma unroll
            for (int jj = 0; jj < 4; jj++) s[i][jj] = 0.f;

        #pragma unroll 4
        for (int c = 0; c < CQK_; c++) {
            float a[4], bb[4];
            #pragma unroll
            for (int i = 0; i < 4; i++)  a[i]  = qs[(4*ty + i) * 33 + c];
            #pragma unroll
            for (int jj = 0; jj < 4; jj++) bb[jj] = ks[(4*tx + jj) * 33 + c];
            #pragma unroll
            for (int i = 0; i < 4; i++)
                #pragma unroll
                for (int jj = 0; jj < 4; jj++)
                    s[i][jj] = fmaf(a[i], bb[jj], s[i][jj]);
        }
        #pragma unroll
        for (int i = 0; i < 4; i++) {
            float px = pq[0*TN + 4*ty + i];
            float py = pq[1*TN + 4*ty + i];
            float pz = pq[2*TN + 4*ty + i];
            #pragma unroll
            for (int jj = 0; jj < 4; jj++) {
                float d = px * pk[0*TM + 4*tx + jj]
                        + py * pk[1*TM + 4*tx + jj]
                        + pz * pk[2*TM + 4*tx + jj];
                s[i][jj] += 0.1f * d;
            }
        }
        #pragma unroll
        for (int i = 0; i < 4; i++)
            #pragma unroll
            for (int jj = 0; jj < 4; jj++)
                S[(4*ty + i) * 65 + 4*tx + jj] = s[i][jj];
        __syncthreads();

        // ---- row stats + exp (online softmax) ----
        if (t < TN) {
            int r = t;
            float old = Mrow[r];
            float mx  = old;
            #pragma unroll 8
            for (int jj = 0; jj < TM; jj++) mx = fmaxf(mx, S[r * 65 + jj]);
            float rs  = __expf(old - mx);
            float sum = 0.f;
            #pragma unroll 8
            for (int jj = 0; jj < TM; jj++) {
                float p = __expf(S[r * 65 + jj] - mx);
                S[r * 65 + jj] = p;
                sum += p;
            }
            Lrow[r] = Lrow[r] * rs + sum;
            Mrow[r] = mx;
            rsc[r]  = rs;
        }
        __syncthreads();

        // ---- rescale accumulators ----
        #pragma unroll
        for (int qi = 0; qi < 8; qi++) {
            float rr = rsc[w * 8 + qi];
            acc[qi][0] *= rr; acc[qi][1] *= rr;
            acc[qi][2] *= rr; acc[qi][3] *= rr;
        }

        // ---- phase B: acc += P * V (float4 V, broadcast P) ----
        #pragma unroll 2
        for (int m = 0; m < TM; m++) {
            float4 v4 = *reinterpret_cast<const float4*>(&vs[m * 132 + 4 * l]);
            #pragma unroll
            for (int qi = 0; qi < 8; qi++) {
                float p = S[(w * 8 + qi) * 65 + m];
                acc[qi][0] = fmaf(p, v4.x, acc[qi][0]);
                acc[qi][1] = fmaf(p, v4.y, acc[qi][1]);
                acc[qi][2] = fmaf(p, v4.z, acc[qi][2]);
                acc[qi][3] = fmaf(p, v4.w, acc[qi][3]);
            }
        }
    }

    // ---- epilogue: out = gamma * acc / L + x, transposed store via smem ----
    float gm = gamma[0];
    float fac[8];
    #pragma unroll
    for (int qi = 0; qi < 8; qi++) fac[qi] = gm / Lrow[w * 8 + qi];

    const float* xb = x + b * C_ * N_;
    #pragma unroll
    for (int cg = 0; cg < 2; cg++) {
        __syncthreads();   // S free to reuse as staging
        if ((l >> 4) == cg) {
            #pragma unroll
            for (int qi = 0; qi < 8; qi++)
                #pragma unroll
                for (int e = 0; e < 4; e++)
                    S[(w * 8 + qi) * 65 + (4 * l + e - cg * 64)] = acc[qi][e] * fac[qi];
        }
        __syncthreads();
        for (int idx = t; idx < 64 * 64; idx += 256) {
            int cl = idx >> 6, nl = idx & 63;
            int c  = cg * 64 + cl;
            out[(b * C_ + c) * N_ + n0 + nl] =
                S[nl * 65 + cl] + xb[c * N_ + n0 + nl];
        }
    }
}

// ===========================================================================
extern "C" void kernel_launch(void* const* d_in, const int* in_sizes, int n_in,
                              void* d_out, int out_size)
{
    (void)in_sizes; (void)n_in; (void)out_size;
    const float* x     = (const float*)d_in[0];
    const float* xyz   = (const float*)d_in[1];
    const float* Wq    = (const float*)d_in[2];
    const float* bq    = (const float*)d_in[3];
    const float* Wk    = (const float*)d_in[4];
    const float* bk    = (const float*)d_in[5];
    const float* Wv    = (const float*)d_in[6];
    const float* bv    = (const float*)d_in[7];
    const float* gamma = (const float*)d_in[8];
    float* out = (float*)d_out;

    // opt-in to >48KB dynamic smem (idempotent, not a stream op — capture-safe)
    cudaFuncSetAttribute(attn_kernel,
                         cudaFuncAttributeMaxDynamicSharedMemorySize,
                         SMEM_FLOATS * (int)sizeof(float));

    dim3 pg(N_ / 32, B_);
    proj_kernel<<<pg, 256>>>(x, xyz, Wq, bq, Wk, bk, Wv, bv);

    dim3 ag(N_ / TN, B_);
    attn_kernel<<<ag, 256, SMEM_FLOATS * sizeof(float)>>>(x, gamma, out);
}

// round 9
// speedup vs baseline: 1.0009x; 1.0005x over previous
#include <cuda_runtime.h>
#include <math.h>

#define B_    4
#define C_    128
#define N_    8192
#define CQK_  32
#define TN    64
#define TM    64

// -------- device scratch (allocation-free rule: __device__ globals) --------
__device__ float g_q  [B_ * CQK_ * N_];   // (B, 32, N)
__device__ float g_k  [B_ * CQK_ * N_];   // (B, 32, N)
__device__ float g_vt [B_ * N_   * C_];   // (B, N, 128)  V transposed
__device__ float g_pos[B_ * 3    * N_];   // (B, 3, N)    normalized xyz

// ===========================================================================
// Projection kernel: q = Wq x + bq, k = Wk x + bk, v = Wv x + bv (transposed),
// plus xyz normalization. One CTA handles 32 points of one batch.
// ===========================================================================
__global__ __launch_bounds__(256) void proj_kernel(
    const float* __restrict__ x,  const float* __restrict__ xyz,
    const float* __restrict__ Wq, const float* __restrict__ bq,
    const float* __restrict__ Wk, const float* __restrict__ bk,
    const float* __restrict__ Wv, const float* __restrict__ bv)
{
    __shared__ float xs [32][132];   // x tile, [point][channel], padded
    __shared__ float stg[32][129];   // V transpose staging

    const int b  = blockIdx.y;
    const int n0 = blockIdx.x * 32;
    const int t  = threadIdx.x;

    const float* xb = x + b * C_ * N_;
    // load x[:, n0:n0+32] tile (coalesced over n)
    for (int idx = t; idx < C_ * 32; idx += 256) {
        int c = idx >> 5, j = idx & 31;
        xs[j][c] = xb[c * N_ + n0 + j];
    }
    // normalized xyz
    if (t < 32) {
        const float* p = xyz + (b * N_ + n0 + t) * 3;
        float px = p[0], py = p[1], pz = p[2];
        float inv = 1.0f / (sqrtf(px*px + py*py + pz*pz) + 1e-8f);
        g_pos[(b*3 + 0) * N_ + n0 + t] = px * inv;
        g_pos[(b*3 + 1) * N_ + n0 + t] = py * inv;
        g_pos[(b*3 + 2) * N_ + n0 + t] = pz * inv;
    }
    __syncthreads();

    const int j = t & 31;    // point within tile
    const int g = t >> 5;    // output group (warp id)

    // ---- pass 1: q (o<32) and k (o in 32..63), 8 outputs per thread ----
    {
        float acc[8] = {0.f,0.f,0.f,0.f,0.f,0.f,0.f,0.f};
        #pragma unroll 4
        for (int cc = 0; cc < 32; cc++) {
            float4 xv = *reinterpret_cast<const float4*>(&xs[j][cc * 4]);
            #pragma unroll
            for (int i = 0; i < 8; i++) {
                int o = g * 8 + i;
                const float* Wrow = (o < 32) ? (Wq + o * C_) : (Wk + (o - 32) * C_);
                float4 w = *reinterpret_cast<const float4*>(Wrow + cc * 4);
                acc[i] = fmaf(w.x, xv.x, fmaf(w.y, xv.y,
                         fmaf(w.z, xv.z, fmaf(w.w, xv.w, acc[i]))));
            }
        }
        #pragma unroll
        for (int i = 0; i < 8; i++) {
            int o = g * 8 + i;
            if (o < 32) g_q[(b * CQK_ +  o      ) * N_ + n0 + j] = acc[i] + bq[o];
            else        g_k[(b * CQK_ + (o - 32)) * N_ + n0 + j] = acc[i] + bk[o - 32];
        }
    }

    // ---- pass 2: v, 16 channels per thread, store transposed via smem ----
    {
        float acc[16];
        #pragma unroll
        for (int i = 0; i < 16; i++) acc[i] = 0.f;
        #pragma unroll 2
        for (int cc = 0; cc < 32; cc++) {
            float4 xv = *reinterpret_cast<const float4*>(&xs[j][cc * 4]);
            #pragma unroll
            for (int i = 0; i < 16; i++) {
                const float* Wrow = Wv + (g * 16 + i) * C_;
                float4 w = *reinterpret_cast<const float4*>(Wrow + cc * 4);
                acc[i] = fmaf(w.x, xv.x, fmaf(w.y, xv.y,
                         fmaf(w.z, xv.z, fmaf(w.w, xv.w, acc[i]))));
            }
        }
        #pragma unroll
        for (int i = 0; i < 16; i++)
            stg[j][g * 16 + i] = acc[i] + bv[g * 16 + i];
        __syncthreads();
        // coalesced transposed store: g_vt[b][n][c]
        for (int idx = t; idx < 32 * C_; idx += 256) {
            int jj = idx >> 7, c = idx & 127;
            g_vt[(b * N_ + n0 + jj) * C_ + c] = stg[jj][c];
        }
    }
}

// ===========================================================================
// Fused flash-attention kernel. One CTA = 64 queries of one batch.
// smem floats: qs 64*33 | ks 64*33 | vs 64*132 | S 64*65 | pq 3*64 | pk 3*64
//              | Mrow 64 | Lrow 64 | rsc 64   == 17408 floats (69632 B)
// ===========================================================================
#define SMEM_FLOATS (TN*33 + TM*33 + TM*132 + TN*65 + 3*TN + 3*TM + 3*TN)

__global__ __launch_bounds__(256, 2) void attn_kernel(
    const float* __restrict__ x, const float* __restrict__ gamma,
    float* __restrict__ out)
{
    extern __shared__ float sm[];
    float* qs   = sm;                 // [64][33]
    float* ks   = qs + TN * 33;      // [64][33]
    float* vs   = ks + TM * 33;      // [64][132]
    float* S    = vs + TM * 132;     // [64][65]  scores -> probs -> out staging
    float* pq   = S  + TN * 65;      // [3][64]
    float* pk   = pq + 3 * TN;       // [3][64]
    float* Mrow = pk + 3 * TM;       // [64]
    float* Lrow = Mrow + TN;         // [64]
    float* rsc  = Lrow + TN;         // [64]

    const int b  = blockIdx.y;
    const int n0 = blockIdx.x * TN;
    const int t  = threadIdx.x;
    const int w  = t >> 5, l = t & 31;
    const int tx = t & 15, ty = t >> 4;

    // load Q tile (coalesced over n)
    const float* qb = g_q + b * CQK_ * N_;
    for (int idx = t; idx < TN * CQK_; idx += 256) {
        int c = idx >> 6, r = idx & 63;
        qs[r * 33 + c] = qb[c * N_ + n0 + r];
    }
    if (t < TN) {
        pq[0*TN + t] = g_pos[(b*3 + 0) * N_ + n0 + t];
        pq[1*TN + t] = g_pos[(b*3 + 1) * N_ + n0 + t];
        pq[2*TN + t] = g_pos[(b*3 + 2) * N_ + n0 + t];
        Mrow[t] = -1e30f;
        Lrow[t] = 0.f;
    }

    float acc[8][4];
    #pragma unroll
    for (int i = 0; i < 8; i++)
        #pragma unroll
        for (int e = 0; e < 4; e++) acc[i][e] = 0.f;

    const float* kb = g_k + b * CQK_ * N_;

    for (int m0 = 0; m0 < N_; m0 += TM) {
        __syncthreads();   // previous iteration's consumers done with ks/vs/S

        // load K tile
        for (int idx = t; idx < TM * CQK_; idx += 256) {
            int c = idx >> 6, r = idx & 63;
            ks[r * 33 + c] = kb[c * N_ + m0 + r];
        }
        // load V tile (transposed source -> conflict-free float4 STS)
        for (int idx = t; idx < TM * 32; idx += 256) {
            int m = idx >> 5, c4 = (idx & 31) << 2;
            float4 v = *reinterpret_cast<const float4*>(
                &g_vt[(b * N_ + m0 + m) * C_ + c4]);
            *reinterpret_cast<float4*>(&vs[m * 132 + c4]) = v;
        }
        if (t < TM) {
            pk[0*TM + t] = g_pos[(b*3 + 0) * N_ + m0 + t];
            pk[1*TM + t] = g_pos[(b*3 + 1) * N_ + m0 + t];
            pk[2*TM + t] = g_pos[(b*3 + 2) * N_ + m0 + t];
        }
        __syncthreads();

        // ---- phase A: S = Q K^T + 0.1 * pos_corr (4x4 register block) ----
        float s[4][4];
        #pragma unroll
        for (int i = 0; i < 4; i++)
            #pragma unroll
            for (int jj = 0; jj < 4; jj++) s[i][jj] = 0.f;

        #pragma unroll 4
        for (int c = 0; c < CQK_; c++) {
            float a[4], bb[4];
            #pragma unroll
            for (int i = 0; i < 4; i++)  a[i]  = qs[(4*ty + i) * 33 + c];
            #pragma unroll
            for (int jj = 0; jj < 4; jj++) bb[jj] = ks[(4*tx + jj) * 33 + c];
            #pragma unroll
            for (int i = 0; i < 4; i++)
                #pragma unroll
                for (int jj = 0; jj < 4; jj++)
                    s[i][jj] = fmaf(a[i], bb[jj], s[i][jj]);
        }
        #pragma unroll
        for (int i = 0; i < 4; i++) {
            float px = pq[0*TN + 4*ty + i];
            float py = pq[1*TN + 4*ty + i];
            float pz = pq[2*TN + 4*ty + i];
            #pragma unroll
            for (int jj = 0; jj < 4; jj++) {
                float d = px * pk[0*TM + 4*tx + jj]
                        + py * pk[1*TM + 4*tx + jj]
                        + pz * pk[2*TM + 4*tx + jj];
                s[i][jj] += 0.1f * d;
            }
        }
        #pragma unroll
        for (int i = 0; i < 4; i++)
            #pragma unroll
            for (int jj = 0; jj < 4; jj++)
                S[(4*ty + i) * 65 + 4*tx + jj] = s[i][jj];
        __syncthreads();

        // ---- row stats + exp (online softmax) ----
        if (t < TN) {
            int r = t;
            float old = Mrow[r];
            float mx  = old;
            #pragma unroll 8
            for (int jj = 0; jj < TM; jj++) mx = fmaxf(mx, S[r * 65 + jj]);
            float rs  = __expf(old - mx);
            float sum = 0.f;
            #pragma unroll 8
            for (int jj = 0; jj < TM; jj++) {
                float p = __expf(S[r * 65 + jj] - mx);
                S[r * 65 + jj] = p;
                sum += p;
            }
            Lrow[r] = Lrow[r] * rs + sum;
            Mrow[r] = mx;
            rsc[r]  = rs;
        }
        __syncthreads();

        // ---- rescale accumulators ----
        #pragma unroll
        for (int qi = 0; qi < 8; qi++) {
            float rr = rsc[w * 8 + qi];
            acc[qi][0] *= rr; acc[qi][1] *= rr;
            acc[qi][2] *= rr; acc[qi][3] *= rr;
        }

        // ---- phase B: acc += P * V (float4 V, broadcast P) ----
        #pragma unroll 2
        for (int m = 0; m < TM; m++) {
            float4 v4 = *reinterpret_cast<const float4*>(&vs[m * 132 + 4 * l]);
            #pragma unroll
            for (int qi = 0; qi < 8; qi++) {
                float p = S[(w * 8 + qi) * 65 + m];
                acc[qi][0] = fmaf(p, v4.x, acc[qi][0]);
                acc[qi][1] = fmaf(p, v4.y, acc[qi][1]);
                acc[qi][2] = fmaf(p, v4.z, acc[qi][2]);
                acc[qi][3] = fmaf(p, v4.w, acc[qi][3]);
            }
        }
    }

    // ---- epilogue: out = gamma * acc / L + x, transposed store via smem ----
    float gm = gamma[0];
    float fac[8];
    #pragma unroll
    for (int qi = 0; qi < 8; qi++) fac[qi] = gm / Lrow[w * 8 + qi];

    const float* xb = x + b * C_ * N_;
    #pragma unroll
    for (int cg = 0; cg < 2; cg++) {
        __syncthreads();   // S free to reuse as staging
        if ((l >> 4) == cg) {
            #pragma unroll
            for (int qi = 0; qi < 8; qi++)
                #pragma unroll
                for (int e = 0; e < 4; e++)
                    S[(w * 8 + qi) * 65 + (4 * l + e - cg * 64)] = acc[qi][e] * fac[qi];
        }
        __syncthreads();
        for (int idx = t; idx < 64 * 64; idx += 256) {
            int cl = idx >> 6, nl = idx & 63;
            int c  = cg * 64 + cl;
            out[(b * C_ + c) * N_ + n0 + nl] =
                S[nl * 65 + cl] + xb[c * N_ + n0 + nl];
        }
    }
}

// ===========================================================================
extern "C" void kernel_launch(void* const* d_in, const int* in_sizes, int n_in,
                              void* d_out, int out_size)
{
    (void)in_sizes; (void)n_in; (void)out_size;
    const float* x     = (const float*)d_in[0];
    const float* xyz   = (const float*)d_in[1];
    const float* Wq    = (const float*)d_in[2];
    const float* bq    = (const float*)d_in[3];
    const float* Wk    = (const float*)d_in[4];
    const float* bk    = (const float*)d_in[5];
    const float* Wv    = (const float*)d_in[6];
    const float* bv    = (const float*)d_in[7];
    const float* gamma = (const float*)d_in[8];
    float* out = (float*)d_out;

    // opt-in to >48KB dynamic smem (idempotent, not a stream op — capture-safe)
    cudaFuncSetAttribute(attn_kernel,
                         cudaFuncAttributeMaxDynamicSharedMemorySize,
                         SMEM_FLOATS * (int)sizeof(float));

    dim3 pg(N_ / 32, B_);
    proj_kernel<<<pg, 256>>>(x, xyz, Wq, bq, Wk, bk, Wv, bv);

    dim3 ag(N_ / TN, B_);
    attn_kernel<<<ag, 256, SMEM_FLOATS * sizeof(float)>>>(x, gamma, out);
}

// round 10
// speedup vs baseline: 1.0011x; 1.0002x over previous
#include <cuda_runtime.h>
#include <math.h>

#define B_    4
#define C_    128
#define N_    8192
#define CQK_  32
#define TN    64
#define TM    64

// -------- device scratch (allocation-free rule: __device__ globals) --------
__device__ float g_q  [B_ * CQK_ * N_];   // (B, 32, N)
__device__ float g_k  [B_ * CQK_ * N_];   // (B, 32, N)
__device__ float g_vt [B_ * N_   * C_];   // (B, N, 128)  V transposed
__device__ float g_pos[B_ * 3    * N_];   // (B, 3, N)    normalized xyz

// ===========================================================================
// Projection kernel: q = Wq x + bq, k = Wk x + bk, v = Wv x + bv (transposed),
// plus xyz normalization. One CTA handles 32 points of one batch.
// ===========================================================================
__global__ __launch_bounds__(256) void proj_kernel(
    const float* __restrict__ x,  const float* __restrict__ xyz,
    const float* __restrict__ Wq, const float* __restrict__ bq,
    const float* __restrict__ Wk, const float* __restrict__ bk,
    const float* __restrict__ Wv, const float* __restrict__ bv)
{
    __shared__ float xs [32][132];   // x tile, [point][channel], padded
    __shared__ float stg[32][129];   // V transpose staging

    const int b  = blockIdx.y;
    const int n0 = blockIdx.x * 32;
    const int t  = threadIdx.x;

    const float* xb = x + b * C_ * N_;
    // load x[:, n0:n0+32] tile (coalesced over n)
    for (int idx = t; idx < C_ * 32; idx += 256) {
        int c = idx >> 5, j = idx & 31;
        xs[j][c] = xb[c * N_ + n0 + j];
    }
    // normalized xyz
    if (t < 32) {
        const float* p = xyz + (b * N_ + n0 + t) * 3;
        float px = p[0], py = p[1], pz = p[2];
        float inv = 1.0f / (sqrtf(px*px + py*py + pz*pz) + 1e-8f);
        g_pos[(b*3 + 0) * N_ + n0 + t] = px * inv;
        g_pos[(b*3 + 1) * N_ + n0 + t] = py * inv;
        g_pos[(b*3 + 2) * N_ + n0 + t] = pz * inv;
    }
    __syncthreads();

    const int j = t & 31;    // point within tile
    const int g = t >> 5;    // output group (warp id)

    // ---- pass 1: q (o<32) and k (o in 32..63), 8 outputs per thread ----
    {
        float acc[8] = {0.f,0.f,0.f,0.f,0.f,0.f,0.f,0.f};
        #pragma unroll 4
        for (int cc = 0; cc < 32; cc++) {
            float4 xv = *reinterpret_cast<const float4*>(&xs[j][cc * 4]);
            #pragma unroll
            for (int i = 0; i < 8; i++) {
                int o = g * 8 + i;
                const float* Wrow = (o < 32) ? (Wq + o * C_) : (Wk + (o - 32) * C_);
                float4 w = *reinterpret_cast<const float4*>(Wrow + cc * 4);
                acc[i] = fmaf(w.x, xv.x, fmaf(w.y, xv.y,
                         fmaf(w.z, xv.z, fmaf(w.w, xv.w, acc[i]))));
            }
        }
        #pragma unroll
        for (int i = 0; i < 8; i++) {
            int o = g * 8 + i;
            if (o < 32) g_q[(b * CQK_ +  o      ) * N_ + n0 + j] = acc[i] + bq[o];
            else        g_k[(b * CQK_ + (o - 32)) * N_ + n0 + j] = acc[i] + bk[o - 32];
        }
    }

    // ---- pass 2: v, 16 channels per thread, store transposed via smem ----
    {
        float acc[16];
        #pragma unroll
        for (int i = 0; i < 16; i++) acc[i] = 0.f;
        #pragma unroll 2
        for (int cc = 0; cc < 32; cc++) {
            float4 xv = *reinterpret_cast<const float4*>(&xs[j][cc * 4]);
            #pragma unroll
            for (int i = 0; i < 16; i++) {
                const float* Wrow = Wv + (g * 16 + i) * C_;
                float4 w = *reinterpret_cast<const float4*>(Wrow + cc * 4);
                acc[i] = fmaf(w.x, xv.x, fmaf(w.y, xv.y,
                         fmaf(w.z, xv.z, fmaf(w.w, xv.w, acc[i]))));
            }
        }
        #pragma unroll
        for (int i = 0; i < 16; i++)
            stg[j][g * 16 + i] = acc[i] + bv[g * 16 + i];
        __syncthreads();
        // coalesced transposed store: g_vt[b][n][c]
        for (int idx = t; idx < 32 * C_; idx += 256) {
            int jj = idx >> 7, c = idx & 127;
            g_vt[(b * N_ + n0 + jj) * C_ + c] = stg[jj][c];
        }
    }
}

// ===========================================================================
// Fused flash-attention kernel. One CTA = 64 queries of one batch.
// smem floats: qs 64*33 | ks 64*33 | vs 64*132 | S 64*65 | pq 3*64 | pk 3*64
//              | Mrow 64 | Lrow 64 | rsc 64   == 17408 floats (69632 B)
// ===========================================================================
#define SMEM_FLOATS (TN*33 + TM*33 + TM*132 + TN*65 + 3*TN + 3*TM + 3*TN)

__global__ __launch_bounds__(256, 2) void attn_kernel(
    const float* __restrict__ x, const float* __restrict__ gamma,
    float* __restrict__ out)
{
    extern __shared__ float sm[];
    float* qs   = sm;                 // [64][33]
    float* ks   = qs + TN * 33;      // [64][33]
    float* vs   = ks + TM * 33;      // [64][132]
    float* S    = vs + TM * 132;     // [64][65]  scores -> probs -> out staging
    float* pq   = S  + TN * 65;      // [3][64]
    float* pk   = pq + 3 * TN;       // [3][64]
    float* Mrow = pk + 3 * TM;       // [64]
    float* Lrow = Mrow + TN;         // [64]
    float* rsc  = Lrow + TN;         // [64]

    const int b  = blockIdx.y;
    const int n0 = blockIdx.x * TN;
    const int t  = threadIdx.x;
    const int w  = t >> 5, l = t & 31;
    const int tx = t & 15, ty = t >> 4;

    // load Q tile (coalesced over n)
    const float* qb = g_q + b * CQK_ * N_;
    for (int idx = t; idx < TN * CQK_; idx += 256) {
        int c = idx >> 6, r = idx & 63;
        qs[r * 33 + c] = qb[c * N_ + n0 + r];
    }
    if (t < TN) {
        pq[0*TN + t] = g_pos[(b*3 + 0) * N_ + n0 + t];
        pq[1*TN + t] = g_pos[(b*3 + 1) * N_ + n0 + t];
        pq[2*TN + t] = g_pos[(b*3 + 2) * N_ + n0 + t];
        Mrow[t] = -1e30f;
        Lrow[t] = 0.f;
    }

    float acc[8][4];
    #pragma unroll
    for (int i = 0; i < 8; i++)
        #pragma unroll
        for (int e = 0; e < 4; e++) acc[i][e] = 0.f;

    const float* kb = g_k + b * CQK_ * N_;

    for (int m0 = 0; m0 < N_; m0 += TM) {
        __syncthreads();   // previous iteration's consumers done with ks/vs/S

        // load K tile
        for (int idx = t; idx < TM * CQK_; idx += 256) {
            int c = idx >> 6, r = idx & 63;
            ks[r * 33 + c] = kb[c * N_ + m0 + r];
        }
        // load V tile (transposed source -> conflict-free float4 STS)
        for (int idx = t; idx < TM * 32; idx += 256) {
            int m = idx >> 5, c4 = (idx & 31) << 2;
            float4 v = *reinterpret_cast<const float4*>(
                &g_vt[(b * N_ + m0 + m) * C_ + c4]);
            *reinterpret_cast<float4*>(&vs[m * 132 + c4]) = v;
        }
        if (t < TM) {
            pk[0*TM + t] = g_pos[(b*3 + 0) * N_ + m0 + t];
            pk[1*TM + t] = g_pos[(b*3 + 1) * N_ + m0 + t];
            pk[2*TM + t] = g_pos[(b*3 + 2) * N_ + m0 + t];
        }
        __syncthreads();

        // ---- phase A: S = Q K^T + 0.1 * pos_corr (4x4 register block) ----
        float s[4][4];
        #pragma unroll
        for (int i = 0; i < 4; i++)
            #pragma unroll
            for (int jj = 0; jj < 4; jj++) s[i][jj] = 0.f;

        #pragma unroll 4
        for (int c = 0; c < CQK_; c++) {
            float a[4], bb[4];
            #pragma unroll
            for (int i = 0; i < 4; i++)  a[i]  = qs[(4*ty + i) * 33 + c];
            #pragma unroll
            for (int jj = 0; jj < 4; jj++) bb[jj] = ks[(4*tx + jj) * 33 + c];
            #pragma unroll
            for (int i = 0; i < 4; i++)
                #pragma unroll
                for (int jj = 0; jj < 4; jj++)
                    s[i][jj] = fmaf(a[i], bb[jj], s[i][jj]);
        }
        #pragma unroll
        for (int i = 0; i < 4; i++) {
            float px = pq[0*TN + 4*ty + i];
            float py = pq[1*TN + 4*ty + i];
            float pz = pq[2*TN + 4*ty + i];
            #pragma unroll
            for (int jj = 0; jj < 4; jj++) {
                float d = px * pk[0*TM + 4*tx + jj]
                        + py * pk[1*TM + 4*tx + jj]
                        + pz * pk[2*TM + 4*tx + jj];
                s[i][jj] += 0.1f * d;
            }
        }
        #pragma unroll
        for (int i = 0; i < 4; i++)
            #pragma unroll
            for (int jj = 0; jj < 4; jj++)
                S[(4*ty + i) * 65 + 4*tx + jj] = s[i][jj];
        __syncthreads();

        // ---- row stats + exp (online softmax) ----
        if (t < TN) {
            int r = t;
            float old = Mrow[r];
            float mx  = old;
            #pragma unroll 8
            for (int jj = 0; jj < TM; jj++) mx = fmaxf(mx, S[r * 65 + jj]);
            float rs  = __expf(old - mx);
            float sum = 0.f;
            #pragma unroll 8
            for (int jj = 0; jj < TM; jj++) {
                float p = __expf(S[r * 65 + jj] - mx);
                S[r * 65 + jj] = p;
                sum += p;
            }
            Lrow[r] = Lrow[r] * rs + sum;
            Mrow[r] = mx;
            rsc[r]  = rs;
        }
        __syncthreads();

        // ---- rescale accumulators ----
        #pragma unroll
        for (int qi = 0; qi < 8; qi++) {
            float rr = rsc[w * 8 + qi];
            acc[qi][0] *= rr; acc[qi][1] *= rr;
            acc[qi][2] *= rr; acc[qi][3] *= rr;
        }

        // ---- phase B: acc += P * V (float4 V, broadcast P) ----
        #pragma unroll 2
        for (int m = 0; m < TM; m++) {
            float4 v4 = *reinterpret_cast<const float4*>(&vs[m * 132 + 4 * l]);
            #pragma unroll
            for (int qi = 0; qi < 8; qi++) {
                float p = S[(w * 8 + qi) * 65 + m];
                acc[qi][0] = fmaf(p, v4.x, acc[qi][0]);
                acc[qi][1] = fmaf(p, v4.y, acc[qi][1]);
                acc[qi][2] = fmaf(p, v4.z, acc[qi][2]);
                acc[qi][3] = fmaf(p, v4.w, acc[qi][3]);
            }
        }
    }

    // ---- epilogue: out = gamma * acc / L + x, transposed store via smem ----
    float gm = gamma[0];
    float fac[8];
    #pragma unroll
    for (int qi = 0; qi < 8; qi++) fac[qi] = gm / Lrow[w * 8 + qi];

    const float* xb = x + b * C_ * N_;
    #pragma unroll
    for (int cg = 0; cg < 2; cg++) {
        __syncthreads();   // S free to reuse as staging
        if ((l >> 4) == cg) {
            #pragma unroll
            for (int qi = 0; qi < 8; qi++)
                #pragma unroll
                for (int e = 0; e < 4; e++)
                    S[(w * 8 + qi) * 65 + (4 * l + e - cg * 64)] = acc[qi][e] * fac[qi];
        }
        __syncthreads();
        for (int idx = t; idx < 64 * 64; idx += 256) {
            int cl = idx >> 6, nl = idx & 63;
            int c  = cg * 64 + cl;
            out[(b * C_ + c) * N_ + n0 + nl] =
                S[nl * 65 + cl] + xb[c * N_ + n0 + nl];
        }
    }
}

// ===========================================================================
extern "C" void kernel_launch(void* const* d_in, const int* in_sizes, int n_in,
                              void* d_out, int out_size)
{
    (void)in_sizes; (void)n_in; (void)out_size;
    const float* x     = (const float*)d_in[0];
    const float* xyz   = (const float*)d_in[1];
    const float* Wq    = (const float*)d_in[2];
    const float* bq    = (const float*)d_in[3];
    const float* Wk    = (const float*)d_in[4];
    const float* bk    = (const float*)d_in[5];
    const float* Wv    = (const float*)d_in[6];
    const float* bv    = (const float*)d_in[7];
    const float* gamma = (const float*)d_in[8];
    float* out = (float*)d_out;

    // opt-in to >48KB dynamic smem (idempotent, not a stream op — capture-safe)
    cudaFuncSetAttribute(attn_kernel,
                         cudaFuncAttributeMaxDynamicSharedMemorySize,
                         SMEM_FLOATS * (int)sizeof(float));

    dim3 pg(N_ / 32, B_);
    proj_kernel<<<pg, 256>>>(x, xyz, Wq, bq, Wk, bk, Wv, bv);

    dim3 ag(N_ / TN, B_);
    attn_kernel<<<ag, 256, SMEM_FLOATS * sizeof(float)>>>(x, gamma, out);
}

// round 12
// speedup vs baseline: 4.0973x; 4.0927x over previous
#include <cuda_runtime.h>
#include <cuda_bf16.h>
#include <math.h>
#include <stdint.h>

#define B_    4
#define C_    128
#define N_    8192
#define CQK_  32
#define LOG2E 1.4426950408889634f
#define BIAS2 64.0f

// ------------------- device scratch (__device__ globals) -------------------
__device__ __align__(16) __nv_bfloat16 g_qh[B_ * N_ * 64];  // (B,N,64) q hi (log2e-scaled)
__device__ __align__(16) __nv_bfloat16 g_ql[B_ * N_ * 64];  // lo residual
__device__ __align__(16) __nv_bfloat16 g_kh[B_ * N_ * 64];  // (B,N,64) k hi
__device__ __align__(16) __nv_bfloat16 g_kl[B_ * N_ * 64];  // lo residual
__device__ __align__(16) __nv_bfloat16 g_vh[(size_t)B_ * C_ * N_]; // (B,C,N) v bf16

// ------------------------------ helpers -----------------------------------
__device__ __forceinline__ uint32_t smem_u32(const void* p) {
    uint32_t a;
    asm("{ .reg .u64 t; cvta.to.shared.u64 t, %1; cvt.u32.u64 %0, t; }"
        : "=r"(a) : "l"(p));
    return a;
}
__device__ __forceinline__ float ex2f(float x) {
    float y; asm("ex2.approx.ftz.f32 %0, %1;" : "=f"(y) : "f"(x)); return y;
}
__device__ __forceinline__ uint32_t packbf2(float lo, float hi) {
    __nv_bfloat162 h2 = __floats2bfloat162_rn(lo, hi);
    return *reinterpret_cast<uint32_t*>(&h2);
}
__device__ __forceinline__ void split_bf16(float f, __nv_bfloat16& h, __nv_bfloat16& l) {
    h = __float2bfloat16_rn(f);
    l = __float2bfloat16_rn(f - __bfloat162float(h));
}

#define LDSM_X4(r0, r1, r2, r3, addr)                                         \
    asm volatile("ldmatrix.sync.aligned.m8n8.x4.shared.b16 {%0,%1,%2,%3}, [%4];" \
                 : "=r"(r0), "=r"(r1), "=r"(r2), "=r"(r3) : "r"(addr))

#define MMA16816(d, a0, a1, a2, a3, b0, b1)                                   \
    asm volatile("mma.sync.aligned.m16n8k16.row.col.f32.bf16.bf16.f32 "       \
                 "{%0,%1,%2,%3},{%4,%5,%6,%7},{%8,%9},{%0,%1,%2,%3};"         \
                 : "+f"((d)[0]), "+f"((d)[1]), "+f"((d)[2]), "+f"((d)[3])     \
                 : "r"(a0), "r"(a1), "r"(a2), "r"(a3), "r"(b0), "r"(b1))

#define CP_ASYNC16(dst, src)                                                  \
    asm volatile("cp.async.cg.shared.global [%0], [%1], 16;"                  \
                 :: "r"(dst), "l"(src))
#define CP_COMMIT()  asm volatile("cp.async.commit_group;" ::: "memory")
#define CP_WAIT1()   asm volatile("cp.async.wait_group 1;"  ::: "memory")
#define CP_WAIT0()   asm volatile("cp.async.wait_group 0;"  ::: "memory")

// ===========================================================================
// Projection kernel: bf16 hi/lo split Q/K (extended with positional dims,
// log2e folded into Q), bf16 V in natural (B,C,N) layout.
// ===========================================================================
__global__ __launch_bounds__(256) void proj_kernel(
    const float* __restrict__ x,  const float* __restrict__ xyz,
    const float* __restrict__ Wq, const float* __restrict__ bq,
    const float* __restrict__ Wk, const float* __restrict__ bk,
    const float* __restrict__ Wv, const float* __restrict__ bv)
{
    __shared__ float xs[32][132];
    __shared__ __nv_bfloat16 sqh[32][64], sql[32][64], skh[32][64], skl[32][64];

    const int b  = blockIdx.y;
    const int n0 = blockIdx.x * 32;
    const int t  = threadIdx.x;

    const float* xb = x + b * C_ * N_;
    for (int idx = t; idx < C_ * 32; idx += 256) {
        int c = idx >> 5, j = idx & 31;
        xs[j][c] = xb[c * N_ + n0 + j];
    }
    if (t < 32) {
        const float* p = xyz + (b * N_ + n0 + t) * 3;
        float px = p[0], py = p[1], pz = p[2];
        float inv = 1.0f / (sqrtf(px*px + py*py + pz*pz) + 1e-8f);
        float pq[3] = { px*inv, py*inv, pz*inv };
        #pragma unroll
        for (int d = 0; d < 3; d++) {
            split_bf16(LOG2E * 0.1f * pq[d], sqh[t][32+d], sql[t][32+d]);
            split_bf16(pq[d],               skh[t][32+d], skl[t][32+d]);
        }
        __nv_bfloat16 z = __float2bfloat16_rn(0.f);
        for (int d = 35; d < 64; d++) {
            sqh[t][d] = z; sql[t][d] = z; skh[t][d] = z; skl[t][d] = z;
        }
    }
    __syncthreads();

    const int j = t & 31;
    const int g = t >> 5;

    {   // q (o<32) and k (o 32..63), 8 outputs/thread
        float acc[8] = {0,0,0,0,0,0,0,0};
        #pragma unroll 4
        for (int cc = 0; cc < 32; cc++) {
            float4 xv = *reinterpret_cast<const float4*>(&xs[j][cc * 4]);
            #pragma unroll
            for (int i = 0; i < 8; i++) {
                int o = g * 8 + i;
                const float* Wrow = (o < 32) ? (Wq + o * C_) : (Wk + (o - 32) * C_);
                float4 w = *reinterpret_cast<const float4*>(Wrow + cc * 4);
                acc[i] = fmaf(w.x, xv.x, fmaf(w.y, xv.y,
                         fmaf(w.z, xv.z, fmaf(w.w, xv.w, acc[i]))));
            }
        }
        #pragma unroll
        for (int i = 0; i < 8; i++) {
            int o = g * 8 + i;
            if (o < 32)
                split_bf16((acc[i] + bq[o]) * LOG2E, sqh[j][o], sql[j][o]);
            else
                split_bf16(acc[i] + bk[o - 32], skh[j][o - 32], skl[j][o - 32]);
        }
    }
    __syncthreads();

    {   // coalesced copy-out: 32 rows x 8 uint4 per array
        int row = t >> 3, c = t & 7;
        size_t off = ((size_t)(b * N_ + n0 + row)) * 64 + c * 8;
        *(uint4*)(g_qh + off) = *(const uint4*)(&sqh[row][c * 8]);
        *(uint4*)(g_ql + off) = *(const uint4*)(&sql[row][c * 8]);
        *(uint4*)(g_kh + off) = *(const uint4*)(&skh[row][c * 8]);
        *(uint4*)(g_kl + off) = *(const uint4*)(&skl[row][c * 8]);
    }

    {   // v: 16 channels/thread, direct bf16 store (B,C,N)
        float acc[16];
        #pragma unroll
        for (int i = 0; i < 16; i++) acc[i] = 0.f;
        #pragma unroll 2
        for (int cc = 0; cc < 32; cc++) {
            float4 xv = *reinterpret_cast<const float4*>(&xs[j][cc * 4]);
            #pragma unroll
            for (int i = 0; i < 16; i++) {
                const float* Wrow = Wv + (g * 16 + i) * C_;
                float4 w = *reinterpret_cast<const float4*>(Wrow + cc * 4);
                acc[i] = fmaf(w.x, xv.x, fmaf(w.y, xv.y,
                         fmaf(w.z, xv.z, fmaf(w.w, xv.w, acc[i]))));
            }
        }
        #pragma unroll
        for (int i = 0; i < 16; i++) {
            int c = g * 16 + i;
            g_vh[((size_t)b * C_ + c) * N_ + n0 + j] =
                __float2bfloat16_rn(acc[i] + bv[c]);
        }
    }
}

// ===========================================================================
// mma.sync flash attention. 512 threads (16 warps), 256 queries/CTA,
// 64-key chunks, K/V double-buffered via cp.async. Warp w owns q rows
// [16w,16w+16). S and P live entirely in registers; O accumulates in regs.
//
// SMEM bytes (rows padded to 144B for conflict-free ldmatrix):
//   Qh 256*144=36864 | Ql 36864 | KV buf x2: (Kh 9216 | Kl 9216 | V 18432)
//   total 147456. Epilogue reuses KV region.
// ===========================================================================
#define ROWB   144
#define SM_QH  0
#define SM_QL  36864
#define SM_KV  73728
#define KVBUF  36864
#define OFF_KH 0
#define OFF_KL 9216
#define OFF_V  18432
#define SM_TOTAL 147456
#define NCH    (N_ / 64)

__global__ __launch_bounds__(512, 1) void attn_kernel(
    const float* __restrict__ x, const float* __restrict__ gamma,
    float* __restrict__ out)
{
    extern __shared__ __align__(16) char smem[];
    const uint32_t sb = smem_u32(smem);

    const int b   = blockIdx.y;
    const int n0q = blockIdx.x * 256;
    const int t   = threadIdx.x;
    const int w   = t >> 5, l = t & 31;
    const int r8    = l & 7;
    const int half  = (l >> 3) & 1;
    const int quart = l >> 4;

    const __nv_bfloat16* kh_b = g_kh + (size_t)b * N_ * 64;
    const __nv_bfloat16* kl_b = g_kl + (size_t)b * N_ * 64;
    const __nv_bfloat16* v_b  = g_vh + (size_t)b * C_ * N_;

    // ---- stage Q (hi/lo) into padded smem rows ----
    {
        const uint4* qh = (const uint4*)(g_qh + ((size_t)(b * N_ + n0q)) * 64);
        const uint4* ql = (const uint4*)(g_ql + ((size_t)(b * N_ + n0q)) * 64);
        for (int i = t; i < 2048; i += 512) {
            int row = i >> 3, cs = i & 7;
            *(uint4*)(smem + SM_QH + row * ROWB + cs * 16) = qh[i];
            *(uint4*)(smem + SM_QL + row * ROWB + cs * 16) = ql[i];
        }
    }

    // per-lane ldmatrix address components
    const uint32_t aRow  = (uint32_t)((w * 16 + half * 8 + r8) * ROWB); // A (Q rows)
    const uint32_t bRow  = (uint32_t)((quart * 8 + r8) * ROWB);         // B (K/V rows)
    const uint32_t aCol0 = (uint32_t)(quart * 16);                      // A col bytes (per ks add 32)
    const uint32_t bCol0 = (uint32_t)(half * 16);                       // B col bytes (per ks add 32)

    float o[16][4];
    #pragma unroll
    for (int i = 0; i < 16; i++)
        #pragma unroll
        for (int e = 0; e < 4; e++) o[i][e] = 0.f;
    float L0 = 0.f, L1 = 0.f;

    // ---- cp.async issue of one 64-key chunk into buffer bb ----
    auto issue = [&](int ch, int bb) {
        const int m0 = ch * 64;
        const uint32_t base = sb + SM_KV + bb * KVBUF;
        {   // Kh: 512 x 16B
            int row = t >> 3, cs = t & 7;
            CP_ASYNC16(base + OFF_KH + row * ROWB + cs * 16,
                       kh_b + (size_t)(m0 + row) * 64 + cs * 8);
            CP_ASYNC16(base + OFF_KL + row * ROWB + cs * 16,
                       kl_b + (size_t)(m0 + row) * 64 + cs * 8);
        }
        {   // V: 1024 x 16B (rows = channels)
            int row = t >> 3, cs = t & 7;
            CP_ASYNC16(base + OFF_V + row * ROWB + cs * 16,
                       v_b + (size_t)row * N_ + m0 + cs * 8);
            int row2 = row + 64;
            CP_ASYNC16(base + OFF_V + row2 * ROWB + cs * 16,
                       v_b + (size_t)row2 * N_ + m0 + cs * 8);
        }
    };

    issue(0, 0); CP_COMMIT();

    for (int ch = 0; ch < NCH; ch++) {
        const int bb = ch & 1;
        if (ch + 1 < NCH) { issue(ch + 1, bb ^ 1); CP_COMMIT(); CP_WAIT1(); }
        else              { CP_WAIT0(); }
        __syncthreads();

        const uint32_t kbase = sb + SM_KV + bb * KVBUF;

        // ---- QK: S = Qh.Kh + Qh.Kl + Ql.Kh over K=48 (3 k16 steps) ----
        float s[8][4];
        #pragma unroll
        for (int i = 0; i < 8; i++)
            #pragma unroll
            for (int e = 0; e < 4; e++) s[i][e] = 0.f;

        #pragma unroll
        for (int ks = 0; ks < 3; ks++) {
            uint32_t qa0, qa1, qa2, qa3, qb0, qb1, qb2, qb3;
            LDSM_X4(qa0, qa1, qa2, qa3, sb + SM_QH + aRow + aCol0 + ks * 32);
            LDSM_X4(qb0, qb1, qb2, qb3, sb + SM_QL + aRow + aCol0 + ks * 32);
            #pragma unroll
            for (int np = 0; np < 4; np++) {
                uint32_t h0, h1, h2, h3, l0, l1, l2, l3;
                uint32_t boff = np * (16 * ROWB) + bRow + bCol0 + ks * 32;
                LDSM_X4(h0, h1, h2, h3, kbase + OFF_KH + boff);
                LDSM_X4(l0, l1, l2, l3, kbase + OFF_KL + boff);
                MMA16816(s[2*np],     qa0, qa1, qa2, qa3, h0, h1);
                MMA16816(s[2*np],     qb0, qb1, qb2, qb3, h0, h1);
                MMA16816(s[2*np],     qa0, qa1, qa2, qa3, l0, l1);
                MMA16816(s[2*np + 1], qa0, qa1, qa2, qa3, h2, h3);
                MMA16816(s[2*np + 1], qb0, qb1, qb2, qb3, h2, h3);
                MMA16816(s[2*np + 1], qa0, qa1, qa2, qa3, l2, l3);
            }
        }

        // ---- fixed-bias softmax: p = exp2(s - 64); repack S-frags -> A-frags ----
        uint32_t pa[4][4];
        float rs0 = 0.f, rs1 = 0.f;
        #pragma unroll
        for (int nt = 0; nt < 8; nt++) {
            float p0 = ex2f(s[nt][0] - BIAS2);
            float p1 = ex2f(s[nt][1] - BIAS2);
            float p2 = ex2f(s[nt][2] - BIAS2);
            float p3 = ex2f(s[nt][3] - BIAS2);
            rs0 += p0 + p1;
            rs1 += p2 + p3;
            int kk = nt >> 1;
            if ((nt & 1) == 0) { pa[kk][0] = packbf2(p0, p1); pa[kk][1] = packbf2(p2, p3); }
            else               { pa[kk][2] = packbf2(p0, p1); pa[kk][3] = packbf2(p2, p3); }
        }
        rs0 += __shfl_xor_sync(0xffffffffu, rs0, 1);
        rs0 += __shfl_xor_sync(0xffffffffu, rs0, 2);
        rs1 += __shfl_xor_sync(0xffffffffu, rs1, 1);
        rs1 += __shfl_xor_sync(0xffffffffu, rs1, 2);
        L0 += rs0;
        L1 += rs1;

        // ---- PV: O += P.V  (K=64: 4 k16 steps, 16 channel tiles) ----
        #pragma unroll
        for (int kk = 0; kk < 4; kk++) {
            #pragma unroll
            for (int cp = 0; cp < 8; cp++) {
                uint32_t v0, v1, v2, v3;
                LDSM_X4(v0, v1, v2, v3,
                        kbase + OFF_V + cp * (16 * ROWB) + bRow + bCol0 + kk * 32);
                MMA16816(o[2*cp],     pa[kk][0], pa[kk][1], pa[kk][2], pa[kk][3], v0, v1);
                MMA16816(o[2*cp + 1], pa[kk][0], pa[kk][1], pa[kk][2], pa[kk][3], v2, v3);
            }
        }
        __syncthreads();   // all warps done with buf bb before it is refilled
    }

    // ---- epilogue: out = gamma * O / L + x  (per-warp smem transpose) ----
    const float gm  = __ldg(gamma);
    const float sc0 = gm / L0;
    const float sc1 = gm / L1;
    const int   g   = l >> 2, t4 = l & 3;

    float* buf = (float*)(smem + SM_KV);   // [256][9] floats, KV region dead
    #pragma unroll 1
    for (int ct = 0; ct < 16; ct++) {
        __syncthreads();
        {
            int q0 = w * 16 + g;
            buf[q0 * 9 + 2*t4]           = o[ct][0] * sc0;
            buf[q0 * 9 + 2*t4 + 1]       = o[ct][1] * sc0;
            buf[(q0 + 8) * 9 + 2*t4]     = o[ct][2] * sc1;
            buf[(q0 + 8) * 9 + 2*t4 + 1] = o[ct][3] * sc1;
        }
        __syncthreads();
        for (int i = t; i < 2048; i += 512) {
            int cl = i >> 8, q = i & 255;
            int c  = ct * 8 + cl;
            size_t go = ((size_t)b * C_ + c) * N_ + n0q + q;
            out[go] = buf[q * 9 + cl] + x[go];
        }
    }
}

// ===========================================================================
extern "C" void kernel_launch(void* const* d_in, const int* in_sizes, int n_in,
                              void* d_out, int out_size)
{
    (void)in_sizes; (void)n_in; (void)out_size;
    const float* x     = (const float*)d_in[0];
    const float* xyz   = (const float*)d_in[1];
    const float* Wq    = (const float*)d_in[2];
    const float* bq    = (const float*)d_in[3];
    const float* Wk    = (const float*)d_in[4];
    const float* bk    = (const float*)d_in[5];
    const float* Wv    = (const float*)d_in[6];
    const float* bv    = (const float*)d_in[7];
    const float* gamma = (const float*)d_in[8];
    float* out = (float*)d_out;

    cudaFuncSetAttribute(attn_kernel,
                         cudaFuncAttributeMaxDynamicSharedMemorySize, SM_TOTAL);

    dim3 pg(N_ / 32, B_);
    proj_kernel<<<pg, 256>>>(x, xyz, Wq, bq, Wk, bk, Wv, bv);

    dim3 ag(N_ / 256, B_);
    attn_kernel<<<ag, 512, SM_TOTAL>>>(x, gamma, out);
}